// round 10
// baseline (speedup 1.0000x reference)
#include <cuda_runtime.h>
#include <cuda_bf16.h>
#include <cstdint>
#include <math.h>

#define Bb 8
#define Cc 512
#define CH 128
#define LL 1024
#define BH 32
#define ALPHA 0.088388347648318447f   // 1/sqrt(128)

// ---------------- device scratch ----------------
__device__ float    g_W  [(size_t)BH * LL * LL];      // fp32 scores
__device__ uint32_t g_W2i[(size_t)BH * LL * LL];      // (h,l)-interleaved split softmax(W), row stride LL words
__device__ uint32_t g_c2i[(size_t)Bb * Cc * LL];      // V-role interleaved [head][c][LL words]
__device__ uint32_t g_e2i[(size_t)Bb * Cc * LL];
__device__ uint32_t g_c2T[(size_t)Bb * Cc * LL];      // K/Q-role element-packed transposed [head][l][128]
__device__ uint32_t g_e2T[(size_t)Bb * Cc * LL];
__device__ uint32_t g_t12T[(size_t)Bb * Cc * LL];     // [head][t][128] element-packed
__device__ uint32_t g_t22T[(size_t)Bb * Cc * LL];     // [b][l][512] element-packed
__device__ uint32_t g_cw2[Cc * Cc];                   // [o][c] element-packed
__device__ float    g_x [(size_t)Bb * Cc * LL];
__device__ float    g_stats[2 * Cc];

// ==================== helpers ====================
__device__ __forceinline__ uint32_t smem_u32(const void* p) {
    uint32_t a;
    asm("{ .reg .u64 t; cvta.to.shared.u64 t, %1; cvt.u32.u64 %0, t; }" : "=r"(a) : "l"(p));
    return a;
}
// fp32 -> packed (hi bf16 @[15:0], lo bf16 @[31:16])
__device__ __forceinline__ uint32_t splt(float x) {
    __nv_bfloat16 h = __float2bfloat16_rn(x);
    float hf = __bfloat162float(h);
    __nv_bfloat16 l = __float2bfloat16_rn(x - hf);
    return (uint32_t)__bfloat16_as_ushort(h) | ((uint32_t)__bfloat16_as_ushort(l) << 16);
}
// two packed elems (k, k+1) -> bf16x2 hi-pair and lo-pair
__device__ __forceinline__ void pack2(uint32_t e0, uint32_t e1, uint32_t& h, uint32_t& l) {
    h = __byte_perm(e0, e1, 0x5410);
    l = __byte_perm(e0, e1, 0x7632);
}

#define MMA16(c, a, b) asm volatile( \
    "mma.sync.aligned.m16n8k16.row.col.f32.bf16.bf16.f32 " \
    "{%0,%1,%2,%3},{%4,%5,%6,%7},{%8,%9},{%0,%1,%2,%3};" \
    : "+f"((c)[0]), "+f"((c)[1]), "+f"((c)[2]), "+f"((c)[3]) \
    : "r"((a)[0]), "r"((a)[1]), "r"((a)[2]), "r"((a)[3]), \
      "r"((b)[0]), "r"((b)[1]))

#define LDS4(r, addr) asm volatile("ld.shared.v4.b32 {%0,%1,%2,%3}, [%4];" \
    : "=r"((r)[0]), "=r"((r)[1]), "=r"((r)[2]), "=r"((r)[3]) : "r"(addr))
#define STS32(addr, v) asm volatile("st.shared.b32 [%0], %1;" :: "r"(addr), "r"(v))
#define STS64(addr, a, b) asm volatile("st.shared.v2.b32 [%0], {%1,%2};" \
    :: "r"(addr), "r"(a), "r"(b))

// ---- smem geometry (bytes) ----
// A: hi plane + lo plane, 16 blocks of 512B + 16B pad each (16B-aligned blocks)
#define ABLK 528
#define ATILE 8448
// B: word-interleaved [h0 l0 h1 l1] granules: 32 blocks of 512B + 16B pad (16B-aligned)
#define BBLK 528
#define BTILE 16896
#define SM_BHI (2 * ATILE)
#define SMEMB (2 * ATILE + BTILE)   // 33792 B

// ---- fills: coalesced mapping (R = tid>>4 + 16it, ci = tid&15) ----
// A: blk = (R>>4)*2 + (ci>>3), T = ((R&7)<<2)|(ci&3), w = ((R>>3)&1) + 2*((ci>>2)&1)
__device__ __forceinline__ void fillA_pk(uint32_t su, int tid,
                                         const uint32_t* src, int stride) {
    const int R0 = tid >> 4, ci = tid & 15;
    const uint32_t sub = su + (uint32_t)((ci >> 3) * ABLK
        + ((((R0 & 7) << 2) | (ci & 3)) << 4)
        + ((((R0 >> 3) & 1) + (((ci >> 2) & 1) << 1)) << 2));
    #pragma unroll
    for (int it = 0; it < 8; it++) {
        uint2 p = *(const uint2*)(src + (size_t)(R0 + 16 * it) * stride + 2 * ci);
        uint32_t h, l; pack2(p.x, p.y, h, l);
        uint32_t ad = sub + (uint32_t)(it * 2 * ABLK);
        STS32(ad, h);
        STS32(ad + ATILE, l);
    }
}
__device__ __forceinline__ void fillA_il(uint32_t su, int tid,
                                         const uint32_t* src, int stride) {
    const int R0 = tid >> 4, ci = tid & 15;
    const uint32_t sub = su + (uint32_t)((ci >> 3) * ABLK
        + ((((R0 & 7) << 2) | (ci & 3)) << 4)
        + ((((R0 >> 3) & 1) + (((ci >> 2) & 1) << 1)) << 2));
    #pragma unroll
    for (int it = 0; it < 8; it++) {
        uint2 p = *(const uint2*)(src + (size_t)(R0 + 16 * it) * stride + 2 * ci);
        uint32_t ad = sub + (uint32_t)(it * 2 * ABLK);
        STS32(ad, p.x);
        STS32(ad + ATILE, p.y);
    }
}
// B: blk = (ci>>3)*16 + (R>>3), T = ((R&7)<<2)|(ci&3), 8B half selected by (ci>>2)&1
__device__ __forceinline__ void fillB_pk(uint32_t su, int tid,
                                         const uint32_t* src, int stride) {
    const int R0 = tid >> 4, ci = tid & 15;
    const uint32_t sub = su + (uint32_t)(SM_BHI + ((ci >> 3) * 16 + (R0 >> 3)) * BBLK
        + ((((R0 & 7) << 2) | (ci & 3)) << 4) + (((ci >> 2) & 1) << 3));
    #pragma unroll
    for (int it = 0; it < 8; it++) {
        uint2 p = *(const uint2*)(src + (size_t)(R0 + 16 * it) * stride + 2 * ci);
        uint32_t h, l; pack2(p.x, p.y, h, l);
        STS64(sub + (uint32_t)(it * 2 * BBLK), h, l);
    }
}
__device__ __forceinline__ void fillB_il(uint32_t su, int tid,
                                         const uint32_t* src, int stride) {
    const int R0 = tid >> 4, ci = tid & 15;
    const uint32_t sub = su + (uint32_t)(SM_BHI + ((ci >> 3) * 16 + (R0 >> 3)) * BBLK
        + ((((R0 & 7) << 2) | (ci & 3)) << 4) + (((ci >> 2) & 1) << 3));
    #pragma unroll
    for (int it = 0; it < 8; it++) {
        uint2 p = *(const uint2*)(src + (size_t)(R0 + 16 * it) * stride + 2 * ci);
        STS64(sub + (uint32_t)(it * 2 * BBLK), p.x, p.y);
    }
}

// one 32-K chunk: 2 ksteps x (8 A-LDS4 + 4 B-LDS4 + 48 bf16 MMAs)
__device__ __forceinline__ void chunk_bf(uint32_t su, int wm, int wn, int lane,
                                         float acc[4][4][4]) {
    #pragma unroll
    for (int kt = 0; kt < 2; kt++) {
        uint32_t ah[4][4], al[4][4], bh[4][2], bl[4][2];
        #pragma unroll
        for (int i = 0; i < 4; i++) {
            uint32_t ad = su + (uint32_t)((((wm * 4 + i) << 1) + kt) * ABLK + lane * 16);
            LDS4(ah[i], ad);
            LDS4(al[i], ad + ATILE);
        }
        #pragma unroll
        for (int j = 0; j < 4; j++) {
            uint32_t bd = su + (uint32_t)(SM_BHI + (kt * 16 + wn * 4 + j) * BBLK + lane * 16);
            uint32_t bv[4];
            LDS4(bv, bd);
            bh[j][0] = bv[0]; bl[j][0] = bv[1];
            bh[j][1] = bv[2]; bl[j][1] = bv[3];
        }
        #pragma unroll
        for (int i = 0; i < 4; i++)
            #pragma unroll
            for (int j = 0; j < 4; j++) {
                MMA16(acc[i][j], al[i], bh[j]);
                MMA16(acc[i][j], ah[i], bl[j]);
                MMA16(acc[i][j], ah[i], bh[j]);
            }
    }
}

// ============================================================================
// QK: W[t,s] = ALPHA * sum_c Q[c,t] K[c,s].  Sources transposed element-packed.
// ============================================================================
__global__ __launch_bounds__(256, 2)
void qk_bf(const uint32_t* __restrict__ QT, const uint32_t* __restrict__ KT) {
    __shared__ __align__(16) char smb[SMEMB];
    const int tid = threadIdx.x, w = tid >> 5, lane = tid & 31;
    const int wm = w >> 2, wn = w & 3;
    const int bh = blockIdx.z, t0 = blockIdx.y * 128, s0 = blockIdx.x * 128;
    const uint32_t* Qh = QT + (size_t)bh * LL * CH + (size_t)t0 * CH;
    const uint32_t* Kh = KT + (size_t)bh * LL * CH + (size_t)s0 * CH;
    float* Wh = g_W + (size_t)bh * LL * LL;

    const uint32_t su = smem_u32(smb);
    float acc[4][4][4] = {};

    for (int ch = 0; ch < 4; ch++) {
        const int c0 = ch * 32;
        if (ch > 0) __syncthreads();
        fillA_pk(su, tid, Qh + c0, CH);
        fillB_pk(su, tid, Kh + c0, CH);
        __syncthreads();
        chunk_bf(su, wm, wn, lane, acc);
    }

    const int r = lane >> 2, cb = (lane & 3) * 2;
    #pragma unroll
    for (int i = 0; i < 4; i++) {
        const int row = t0 + wm * 64 + i * 16 + r;
        #pragma unroll
        for (int j = 0; j < 4; j++) {
            const int col = s0 + wn * 32 + j * 8 + cb;
            *(float2*)(Wh + (size_t)row * LL + col) =
                make_float2(acc[i][j][0] * ALPHA, acc[i][j][1] * ALPHA);
            *(float2*)(Wh + (size_t)(row + 8) * LL + col) =
                make_float2(acc[i][j][2] * ALPHA, acc[i][j][3] * ALPHA);
        }
    }
}

// ============================================================================
// AV: Out[c,t] = sum_s W[t,s] V[c,s].  Sources (h,l)-interleaved (row = LL words);
// writes transposed element-packed output for the next consumer.
// cs = 128: t12T [head][t][128];  cs = 512: t22T [b][l][512]
// ============================================================================
__global__ __launch_bounds__(256, 2)
void av_bf(const uint32_t* __restrict__ Vi, uint32_t* __restrict__ OutT, int cs) {
    __shared__ __align__(16) char smb[SMEMB];
    const int tid = threadIdx.x, w = tid >> 5, lane = tid & 31;
    const int wm = w >> 2, wn = w & 3;
    const int bh = blockIdx.z, t0 = blockIdx.x * 128;
    const uint32_t* Vh = Vi + (size_t)bh * CH * LL;
    const uint32_t* Wh = g_W2i + (size_t)bh * LL * LL + (size_t)t0 * LL;

    const uint32_t su = smem_u32(smb);
    float acc[4][4][4] = {};

    for (int ch = 0; ch < 32; ch++) {
        const int s0 = ch * 32;     // word offset == element offset
        if (ch > 0) __syncthreads();
        fillA_il(su, tid, Vh + s0, LL);
        fillB_il(su, tid, Wh + s0, LL);
        __syncthreads();
        chunk_bf(su, wm, wn, lane, acc);
    }

    size_t obase; int rowofs;
    if (cs == 128) { obase = (size_t)bh * (1024 * 128); rowofs = 0; }
    else           { obase = (size_t)(bh >> 2) * (1024 * 512); rowofs = (bh & 3) * 128; }
    uint32_t* O = OutT + obase + rowofs;

    const int r = lane >> 2, cb = (lane & 3) * 2;
    #pragma unroll
    for (int i = 0; i < 4; i++) {
        const int row = wm * 64 + i * 16 + r;
        #pragma unroll
        for (int j = 0; j < 4; j++) {
            const int col = t0 + wn * 32 + j * 8 + cb;
            O[(size_t)col * cs + row]           = splt(acc[i][j][0]);
            O[(size_t)(col + 1) * cs + row]     = splt(acc[i][j][1]);
            O[(size_t)col * cs + row + 8]       = splt(acc[i][j][2]);
            O[(size_t)(col + 1) * cs + row + 8] = splt(acc[i][j][3]);
        }
    }
}

// ============================================================================
// conv 1x1: X[o,l] = sum_c Wc[o,c] E[c,l] + bias[o].
// A = cw2 [o][c] element-packed; B = t22T [b][l][512] element-packed.
// ============================================================================
__global__ __launch_bounds__(256, 2)
void conv_bf(const uint32_t* __restrict__ CW, const uint32_t* __restrict__ ET,
             const float* __restrict__ bias) {
    __shared__ __align__(16) char smb[SMEMB];
    const int tid = threadIdx.x, w = tid >> 5, lane = tid & 31;
    const int wm = w >> 2, wn = w & 3;
    const int b = blockIdx.z, o0 = blockIdx.y * 128, l0 = blockIdx.x * 128;
    const uint32_t* Ab = CW + (size_t)o0 * Cc;
    const uint32_t* Bbtile = ET + (size_t)b * LL * Cc + (size_t)l0 * Cc;
    float* Xb = g_x + (size_t)b * Cc * LL;

    const uint32_t su = smem_u32(smb);
    float acc[4][4][4] = {};

    for (int ch = 0; ch < 16; ch++) {
        const int c0 = ch * 32;
        if (ch > 0) __syncthreads();
        fillA_pk(su, tid, Ab + c0, Cc);
        fillB_pk(su, tid, Bbtile + c0, Cc);
        __syncthreads();
        chunk_bf(su, wm, wn, lane, acc);
    }

    const int r = lane >> 2, cb = (lane & 3) * 2;
    #pragma unroll
    for (int i = 0; i < 4; i++) {
        const int o = o0 + wm * 64 + i * 16 + r;
        const float b0 = bias[o], b1 = bias[o + 8];
        #pragma unroll
        for (int j = 0; j < 4; j++) {
            const int col = l0 + wn * 32 + j * 8 + cb;
            *(float2*)(Xb + (size_t)o * LL + col) =
                make_float2(acc[i][j][0] + b0, acc[i][j][1] + b0);
            *(float2*)(Xb + (size_t)(o + 8) * LL + col) =
                make_float2(acc[i][j][2] + b1, acc[i][j][3] + b1);
        }
    }
}

// ============================================================================
// split + transpose builder: fp32 [head][c][l] ->
//   di: (h,l)-interleaved [head][c][LL words], dT: element-packed [head][l][128]
// ============================================================================
__global__ __launch_bounds__(256)
void split_tr(const float* __restrict__ src, uint32_t* __restrict__ di,
              uint32_t* __restrict__ dT) {
    __shared__ uint32_t tsm[32][33];
    const int hh = blockIdx.z;
    const int c0 = blockIdx.y * 32, l0 = blockIdx.x * 32;
    const float* S = src + (size_t)hh * CH * LL;
    const int c = threadIdx.x >> 3, l4 = (threadIdx.x & 7) * 4;

    float4 v = *(const float4*)(S + (size_t)(c0 + c) * LL + l0 + l4);
    uint32_t q0 = splt(v.x), q1 = splt(v.y), q2 = splt(v.z), q3 = splt(v.w);

    uint32_t h0, lo0, h1, lo1;
    pack2(q0, q1, h0, lo0);
    pack2(q2, q3, h1, lo1);
    uint4 wi; wi.x = h0; wi.y = lo0; wi.z = h1; wi.w = lo1;
    *(uint4*)(di + (size_t)hh * CH * LL + (size_t)(c0 + c) * LL + (l0 + l4)) = wi;

    tsm[c][l4 + 0] = q0; tsm[c][l4 + 1] = q1;
    tsm[c][l4 + 2] = q2; tsm[c][l4 + 3] = q3;
    __syncthreads();

    const int l = threadIdx.x >> 3, c4 = (threadIdx.x & 7) * 4;
    uint4 wt;
    wt.x = tsm[c4 + 0][l]; wt.y = tsm[c4 + 1][l];
    wt.z = tsm[c4 + 2][l]; wt.w = tsm[c4 + 3][l];
    *(uint4*)(dT + (size_t)hh * LL * CH + (size_t)(l0 + l) * CH + c0 + c4) = wt;
}

// elementwise split (conv weight)
__global__ __launch_bounds__(256)
void split_k(const float* __restrict__ in, uint32_t* __restrict__ out) {
    const size_t i = ((size_t)blockIdx.x * 256 + threadIdx.x) * 4;
    float4 x = *(const float4*)(in + i);
    uint4 o;
    o.x = splt(x.x); o.y = splt(x.y); o.z = splt(x.z); o.w = splt(x.w);
    *(uint4*)(out + i) = o;
}

// ============================================================================
// Row softmax: fp32 W -> (h,l)-interleaved split, row stride LL words
// ============================================================================
__global__ __launch_bounds__(256)
void softmax_il() {
    const float* p = g_W + (size_t)blockIdx.x * LL;
    uint32_t* q = g_W2i + (size_t)blockIdx.x * LL;
    const int tid = threadIdx.x;
    float4 v = *(const float4*)(p + tid * 4);

    float m = fmaxf(fmaxf(v.x, v.y), fmaxf(v.z, v.w));
    #pragma unroll
    for (int o = 16; o; o >>= 1) m = fmaxf(m, __shfl_xor_sync(~0u, m, o));
    __shared__ float redm[8], reds[8];
    if ((tid & 31) == 0) redm[tid >> 5] = m;
    __syncthreads();
    float mx = redm[0];
    #pragma unroll
    for (int w = 1; w < 8; w++) mx = fmaxf(mx, redm[w]);

    v.x = expf(v.x - mx); v.y = expf(v.y - mx);
    v.z = expf(v.z - mx); v.w = expf(v.w - mx);
    float s = v.x + v.y + v.z + v.w;
    #pragma unroll
    for (int o = 16; o; o >>= 1) s += __shfl_xor_sync(~0u, s, o);
    if ((tid & 31) == 0) reds[tid >> 5] = s;
    __syncthreads();
    float st = 0.f;
    #pragma unroll
    for (int w = 0; w < 8; w++) st += reds[w];

    float inv = 1.0f / st;
    uint32_t q0 = splt(v.x * inv), q1 = splt(v.y * inv);
    uint32_t q2 = splt(v.z * inv), q3 = splt(v.w * inv);
    uint32_t h0, l0, h1, l1;
    pack2(q0, q1, h0, l0);
    pack2(q2, q3, h1, l1);
    uint4 o; o.x = h0; o.y = l0; o.z = h1; o.w = l1;
    *(uint4*)(q + tid * 4) = o;
}

// ============================================================================
// BN stats + normalize + swish
// ============================================================================
__global__ __launch_bounds__(256)
void bn_stats() {
    const int o = blockIdx.x;
    float s = 0.f, sq = 0.f;
    for (int idx = threadIdx.x; idx < Bb * LL; idx += 256) {
        const int b = idx >> 10, l = idx & (LL - 1);
        float x = g_x[((size_t)b * Cc + o) * LL + l];
        s += x; sq += x * x;
    }
    __shared__ float rs[256], rq[256];
    rs[threadIdx.x] = s; rq[threadIdx.x] = sq;
    __syncthreads();
    for (int st = 128; st; st >>= 1) {
        if (threadIdx.x < st) {
            rs[threadIdx.x] += rs[threadIdx.x + st];
            rq[threadIdx.x] += rq[threadIdx.x + st];
        }
        __syncthreads();
    }
    if (threadIdx.x == 0) {
        const float n = (float)(Bb * LL);
        float mean = rs[0] / n;
        float var  = rq[0] / n - mean * mean;
        g_stats[o] = mean;
        g_stats[Cc + o] = rsqrtf(var + 1e-5f);
    }
}

__global__ __launch_bounds__(256)
void bn_swish(const float* __restrict__ gamma, const float* __restrict__ beta,
              float* __restrict__ out) {
    const size_t i = ((size_t)blockIdx.x * blockDim.x + threadIdx.x) * 4;
    const int o = (int)((i >> 10) & (Cc - 1));
    const float m = g_stats[o], is = g_stats[Cc + o];
    const float ga = gamma[o], be = beta[o];
    float4 x = *(const float4*)(g_x + i);
    float4 y;
    { float xn = (x.x - m) * is * ga + be; y.x = xn / (1.f + expf(-xn)); }
    { float xn = (x.y - m) * is * ga + be; y.y = xn / (1.f + expf(-xn)); }
    { float xn = (x.z - m) * is * ga + be; y.z = xn / (1.f + expf(-xn)); }
    { float xn = (x.w - m) * is * ga + be; y.w = xn / (1.f + expf(-xn)); }
    *(float4*)(out + i) = y;
}

// ============================================================================
// launch
// ============================================================================
extern "C" void kernel_launch(void* const* d_in, const int* in_sizes, int n_in,
                              void* d_out, int out_size) {
    const float* c_in   = (const float*)d_in[0];
    const float* e_in   = (const float*)d_in[1];
    const float* conv_w = (const float*)d_in[2];
    const float* conv_b = (const float*)d_in[3];
    const float* gamma  = (const float*)d_in[4];
    const float* beta   = (const float*)d_in[5];
    float* out = (float*)d_out;

    uint32_t *c2i, *e2i, *c2T, *e2T, *t12T, *t22T, *cw2;
    cudaGetSymbolAddress((void**)&c2i,  g_c2i);
    cudaGetSymbolAddress((void**)&e2i,  g_e2i);
    cudaGetSymbolAddress((void**)&c2T,  g_c2T);
    cudaGetSymbolAddress((void**)&e2T,  g_e2T);
    cudaGetSymbolAddress((void**)&t12T, g_t12T);
    cudaGetSymbolAddress((void**)&t22T, g_t22T);
    cudaGetSymbolAddress((void**)&cw2,  g_cw2);

    const int NEL = Bb * Cc * LL;   // 4M

    // builders
    split_tr<<<dim3(32, 4, BH), 256>>>(c_in, c2i, c2T);
    split_tr<<<dim3(32, 4, BH), 256>>>(e_in, e2i, e2T);
    split_k<<<Cc * Cc / 1024, 256>>>(conv_w, cw2);

    // attn1: _c = attn(q=e, k=c, v=c)
    qk_bf<<<dim3(8, 8, BH), 256>>>(e2T, c2T);
    softmax_il<<<BH * LL, 256>>>();
    av_bf<<<dim3(8, 1, BH), 256>>>(c2i, t12T, 128);

    // attn2: _e = attn(q=_c, k=e, v=e)
    qk_bf<<<dim3(8, 8, BH), 256>>>(t12T, e2T);
    softmax_il<<<BH * LL, 256>>>();
    av_bf<<<dim3(8, 1, BH), 256>>>(e2i, t22T, 512);

    // proj: 1x1 conv + bias, then BN + swish
    conv_bf<<<dim3(8, 4, 8), 256>>>(cw2, t22T, conv_b);
    bn_stats<<<Cc, 256>>>();
    bn_swish<<<NEL / 1024, 256>>>(gamma, beta, out);
}

// round 11
// speedup vs baseline: 1.0631x; 1.0631x over previous
#include <cuda_runtime.h>
#include <cuda_bf16.h>
#include <cstdint>
#include <math.h>

#define Bb 8
#define Cc 512
#define CH 128
#define LL 1024
#define BH 32
#define ALPHA 0.088388347648318447f   // 1/sqrt(128)

// ---------------- device scratch ----------------
__device__ float    g_W   [(size_t)BH * LL * LL];     // fp32 scores
__device__ uint32_t g_W2i [(size_t)BH * LL * LL];     // interleaved softmax(W) [bh][t][LL w]
__device__ uint32_t g_c2i [(size_t)Bb * Cc * LL];     // [bh][c][LL w]    (V role)
__device__ uint32_t g_e2i [(size_t)Bb * Cc * LL];
__device__ uint32_t g_c2Ti[(size_t)Bb * Cc * LL];     // [bh][l][CH w]    (QK roles)
__device__ uint32_t g_e2Ti[(size_t)Bb * Cc * LL];
__device__ uint32_t g_t12Ti[(size_t)Bb * Cc * LL];    // [bh][t][CH w]
__device__ uint32_t g_t22Ti[(size_t)Bb * Cc * LL];    // [b][l][Cc w]
__device__ uint32_t g_cw2i[Cc * Cc];                  // [o][Cc w]
__device__ float    g_x  [(size_t)Bb * Cc * LL];
__device__ float    g_stats[2 * Cc];

// ==================== helpers ====================
__device__ __forceinline__ uint32_t smem_u32(const void* p) {
    uint32_t a;
    asm("{ .reg .u64 t; cvta.to.shared.u64 t, %1; cvt.u32.u64 %0, t; }" : "=r"(a) : "l"(p));
    return a;
}
__device__ __forceinline__ uint32_t splt(float x) {
    __nv_bfloat16 h = __float2bfloat16_rn(x);
    float hf = __bfloat162float(h);
    __nv_bfloat16 l = __float2bfloat16_rn(x - hf);
    return (uint32_t)__bfloat16_as_ushort(h) | ((uint32_t)__bfloat16_as_ushort(l) << 16);
}
__device__ __forceinline__ void pack2(uint32_t e0, uint32_t e1, uint32_t& h, uint32_t& l) {
    h = __byte_perm(e0, e1, 0x5410);
    l = __byte_perm(e0, e1, 0x7632);
}

#define MMA16(c, a, b) asm volatile( \
    "mma.sync.aligned.m16n8k16.row.col.f32.bf16.bf16.f32 " \
    "{%0,%1,%2,%3},{%4,%5,%6,%7},{%8,%9},{%0,%1,%2,%3};" \
    : "+f"((c)[0]), "+f"((c)[1]), "+f"((c)[2]), "+f"((c)[3]) \
    : "r"((a)[0]), "r"((a)[1]), "r"((a)[2]), "r"((a)[3]), \
      "r"((b)[0]), "r"((b)[1]))

#define LDS4(r, addr) asm volatile("ld.shared.v4.b32 {%0,%1,%2,%3}, [%4];" \
    : "=r"((r)[0]), "=r"((r)[1]), "=r"((r)[2]), "=r"((r)[3]) : "r"(addr))
#define CPA4(d, s) asm volatile("cp.async.ca.shared.global [%0], [%1], 4;" :: "r"(d), "l"(s))
#define CPA8(d, s) asm volatile("cp.async.ca.shared.global [%0], [%1], 8;" :: "r"(d), "l"(s))
#define CP_COMMIT() asm volatile("cp.async.commit_group;" ::: "memory")
#define CP_WAIT1()  asm volatile("cp.async.wait_group 1;" ::: "memory")
#define CP_WAIT0()  asm volatile("cp.async.wait_group 0;" ::: "memory")

// ---- smem geometry (bytes), per pipeline buffer ----
#define ABLK 528
#define ATILE 8448
#define BBLK 528
#define BTILE 16896
#define SM_BHI (2 * ATILE)
#define SMEMB (2 * ATILE + BTILE)          // 33792 per buffer
#define SMEM_TOTAL (2 * SMEMB)             // 67584 double-buffered

// ---- async fills (sources are (h,l)-interleaved, 1 word/elem) ----
__device__ __forceinline__ void fillA_cp(uint32_t su, int tid,
                                         const uint32_t* src, int stride) {
    const int R0 = tid >> 4, ci = tid & 15;
    const uint32_t dst = su + (uint32_t)((ci >> 3) * ABLK
        + ((((R0 & 7) << 2) | (ci & 3)) << 4)
        + ((((R0 >> 3) & 1) + (((ci >> 2) & 1) << 1)) << 2));
    const uint32_t* s = src + (size_t)R0 * stride + 2 * ci;
    #pragma unroll
    for (int it = 0; it < 8; it++) {
        uint32_t ad = dst + (uint32_t)(it * 2 * ABLK);
        CPA4(ad, s);                 // h word -> plane0
        CPA4(ad + ATILE, s + 1);     // l word -> plane1
        s += 16 * stride;
    }
}
__device__ __forceinline__ void fillB_cp(uint32_t su, int tid,
                                         const uint32_t* src, int stride) {
    const int R0 = tid >> 4, ci = tid & 15;
    const uint32_t dst = su + (uint32_t)(SM_BHI + ((ci >> 3) * 16 + (R0 >> 3)) * BBLK
        + ((((R0 & 7) << 2) | (ci & 3)) << 4) + (((ci >> 2) & 1) << 3));
    const uint32_t* s = src + (size_t)R0 * stride + 2 * ci;
    #pragma unroll
    for (int it = 0; it < 8; it++) {
        CPA8(dst + (uint32_t)(it * 2 * BBLK), s);
        s += 16 * stride;
    }
}

// one 32-K chunk: 2 ksteps x (8 A-LDS4 + 4 B-LDS4 + 48 bf16 MMAs)
__device__ __forceinline__ void chunk_bf(uint32_t su, int wm, int wn, int lane,
                                         float acc[4][4][4]) {
    #pragma unroll
    for (int kt = 0; kt < 2; kt++) {
        uint32_t ah[4][4], al[4][4], bh[4][2], bl[4][2];
        #pragma unroll
        for (int i = 0; i < 4; i++) {
            uint32_t ad = su + (uint32_t)((((wm * 4 + i) << 1) + kt) * ABLK + lane * 16);
            LDS4(ah[i], ad);
            LDS4(al[i], ad + ATILE);
        }
        #pragma unroll
        for (int j = 0; j < 4; j++) {
            uint32_t bd = su + (uint32_t)(SM_BHI + (kt * 16 + wn * 4 + j) * BBLK + lane * 16);
            uint32_t bv[4];
            LDS4(bv, bd);
            bh[j][0] = bv[0]; bl[j][0] = bv[1];
            bh[j][1] = bv[2]; bl[j][1] = bv[3];
        }
        #pragma unroll
        for (int i = 0; i < 4; i++)
            #pragma unroll
            for (int j = 0; j < 4; j++) {
                MMA16(acc[i][j], al[i], bh[j]);
                MMA16(acc[i][j], ah[i], bl[j]);
                MMA16(acc[i][j], ah[i], bh[j]);
            }
    }
}

// ============================================================================
// QK: W[t,s] = ALPHA * sum_c Q[c,t] K[c,s].  Sources transposed-interleaved.
// ============================================================================
__global__ __launch_bounds__(256, 2)
void qk_bf(const uint32_t* __restrict__ QTi, const uint32_t* __restrict__ KTi) {
    extern __shared__ __align__(16) char dynsm[];
    const uint32_t su = smem_u32(dynsm);
    const int tid = threadIdx.x, w = tid >> 5, lane = tid & 31;
    const int wm = w >> 2, wn = w & 3;
    const int bh = blockIdx.z, t0 = blockIdx.y * 128, s0 = blockIdx.x * 128;
    const uint32_t* Qs = QTi + (size_t)bh * LL * CH + (size_t)t0 * CH;
    const uint32_t* Ks = KTi + (size_t)bh * LL * CH + (size_t)s0 * CH;
    float* Wh = g_W + (size_t)bh * LL * LL;

    float acc[4][4][4] = {};

    fillA_cp(su, tid, Qs, CH);
    fillB_cp(su, tid, Ks, CH);
    CP_COMMIT();
    for (int ch = 0; ch < 4; ch++) {
        const uint32_t cur = su + (uint32_t)((ch & 1) * SMEMB);
        if (ch < 3) {
            const uint32_t nxt = su + (uint32_t)(((ch + 1) & 1) * SMEMB);
            fillA_cp(nxt, tid, Qs + (ch + 1) * 32, CH);
            fillB_cp(nxt, tid, Ks + (ch + 1) * 32, CH);
            CP_COMMIT();
            CP_WAIT1();
        } else {
            CP_WAIT0();
        }
        __syncthreads();
        chunk_bf(cur, wm, wn, lane, acc);
        if (ch < 3) __syncthreads();
    }

    const int r = lane >> 2, cb = (lane & 3) * 2;
    #pragma unroll
    for (int i = 0; i < 4; i++) {
        const int row = t0 + wm * 64 + i * 16 + r;
        #pragma unroll
        for (int j = 0; j < 4; j++) {
            const int col = s0 + wn * 32 + j * 8 + cb;
            *(float2*)(Wh + (size_t)row * LL + col) =
                make_float2(acc[i][j][0] * ALPHA, acc[i][j][1] * ALPHA);
            *(float2*)(Wh + (size_t)(row + 8) * LL + col) =
                make_float2(acc[i][j][2] * ALPHA, acc[i][j][3] * ALPHA);
        }
    }
}

// ============================================================================
// AV: Out[c,t] = sum_s W[t,s] V[c,s].  Writes transposed-interleaved output.
// cs=128: t12Ti [head][t][128w];  cs=512: t22Ti [b][l][512w]
// ============================================================================
__global__ __launch_bounds__(256, 2)
void av_bf(const uint32_t* __restrict__ Vi, uint32_t* __restrict__ OutT, int cs) {
    extern __shared__ __align__(16) char dynsm[];
    const uint32_t su = smem_u32(dynsm);
    const int tid = threadIdx.x, w = tid >> 5, lane = tid & 31;
    const int wm = w >> 2, wn = w & 3;
    const int bh = blockIdx.z, t0 = blockIdx.x * 128;
    const uint32_t* Vs = Vi + (size_t)bh * CH * LL;
    const uint32_t* Ws = g_W2i + (size_t)bh * LL * LL + (size_t)t0 * LL;

    float acc[4][4][4] = {};

    fillA_cp(su, tid, Vs, LL);
    fillB_cp(su, tid, Ws, LL);
    CP_COMMIT();
    for (int ch = 0; ch < 32; ch++) {
        const uint32_t cur = su + (uint32_t)((ch & 1) * SMEMB);
        if (ch < 31) {
            const uint32_t nxt = su + (uint32_t)(((ch + 1) & 1) * SMEMB);
            fillA_cp(nxt, tid, Vs + (ch + 1) * 32, LL);
            fillB_cp(nxt, tid, Ws + (ch + 1) * 32, LL);
            CP_COMMIT();
            CP_WAIT1();
        } else {
            CP_WAIT0();
        }
        __syncthreads();
        chunk_bf(cur, wm, wn, lane, acc);
        if (ch < 31) __syncthreads();
    }

    size_t obase; int rowofs, CS;
    if (cs == 128) { obase = (size_t)bh * (1024 * 128); rowofs = 0; CS = 128; }
    else           { obase = (size_t)(bh >> 2) * (1024 * 512); rowofs = (bh & 3) * 128; CS = 512; }
    uint32_t* O = OutT + obase;

    const int r = lane >> 2, cb = (lane & 3) * 2;
    const int sel = (lane >> 2) & 1;   // r parity (partner = lane^4)
    #pragma unroll
    for (int i = 0; i < 4; i++) {
        const int c0r = rowofs + wm * 64 + i * 16 + r;
        #pragma unroll
        for (int j = 0; j < 4; j++) {
            const int t = t0 + wn * 32 + j * 8 + cb;
            #pragma unroll
            for (int q = 0; q < 4; q++) {
                const int cc = c0r + ((q >> 1) << 3);
                const int tt = t + (q & 1);
                uint32_t wv = splt(acc[i][j][q]);
                uint32_t wp = __shfl_xor_sync(0xffffffffu, wv, 4);
                uint32_t word = sel ? __byte_perm(wp, wv, 0x7632)
                                    : __byte_perm(wv, wp, 0x5410);
                O[(size_t)tt * CS + (cc & ~1) + sel] = word;
            }
        }
    }
}

// ============================================================================
// conv 1x1: X[o,l] = sum_c Wc[o,c] E[c,l] + bias[o].  Interleaved sources.
// ============================================================================
__global__ __launch_bounds__(256, 2)
void conv_bf(const uint32_t* __restrict__ CW, const uint32_t* __restrict__ ETi,
             const float* __restrict__ bias) {
    extern __shared__ __align__(16) char dynsm[];
    const uint32_t su = smem_u32(dynsm);
    const int tid = threadIdx.x, w = tid >> 5, lane = tid & 31;
    const int wm = w >> 2, wn = w & 3;
    const int b = blockIdx.z, o0 = blockIdx.y * 128, l0 = blockIdx.x * 128;
    const uint32_t* As = CW + (size_t)o0 * Cc;
    const uint32_t* Bs = ETi + (size_t)b * LL * Cc + (size_t)l0 * Cc;
    float* Xb = g_x + (size_t)b * Cc * LL;

    float acc[4][4][4] = {};

    fillA_cp(su, tid, As, Cc);
    fillB_cp(su, tid, Bs, Cc);
    CP_COMMIT();
    for (int ch = 0; ch < 16; ch++) {
        const uint32_t cur = su + (uint32_t)((ch & 1) * SMEMB);
        if (ch < 15) {
            const uint32_t nxt = su + (uint32_t)(((ch + 1) & 1) * SMEMB);
            fillA_cp(nxt, tid, As + (ch + 1) * 32, Cc);
            fillB_cp(nxt, tid, Bs + (ch + 1) * 32, Cc);
            CP_COMMIT();
            CP_WAIT1();
        } else {
            CP_WAIT0();
        }
        __syncthreads();
        chunk_bf(cur, wm, wn, lane, acc);
        if (ch < 15) __syncthreads();
    }

    const int r = lane >> 2, cb = (lane & 3) * 2;
    #pragma unroll
    for (int i = 0; i < 4; i++) {
        const int o = o0 + wm * 64 + i * 16 + r;
        const float b0 = bias[o], b1 = bias[o + 8];
        #pragma unroll
        for (int j = 0; j < 4; j++) {
            const int col = l0 + wn * 32 + j * 8 + cb;
            *(float2*)(Xb + (size_t)o * LL + col) =
                make_float2(acc[i][j][0] + b0, acc[i][j][1] + b0);
            *(float2*)(Xb + (size_t)(o + 8) * LL + col) =
                make_float2(acc[i][j][2] + b1, acc[i][j][3] + b1);
        }
    }
}

// ============================================================================
// builder: fp32 [head][c][l] -> di interleaved [c][LLw], dTi interleaved [l][CHw]
// ============================================================================
__global__ __launch_bounds__(256)
void split_tr(const float* __restrict__ src, uint32_t* __restrict__ di,
              uint32_t* __restrict__ dTi) {
    __shared__ uint32_t tsm[32][33];
    const int hh = blockIdx.z;
    const int c0 = blockIdx.y * 32, l0 = blockIdx.x * 32;
    const float* S = src + (size_t)hh * CH * LL;
    const int c = threadIdx.x >> 3, l4 = (threadIdx.x & 7) * 4;

    float4 v = *(const float4*)(S + (size_t)(c0 + c) * LL + l0 + l4);
    uint32_t q0 = splt(v.x), q1 = splt(v.y), q2 = splt(v.z), q3 = splt(v.w);

    uint32_t h0, w0, h1, w1;
    pack2(q0, q1, h0, w0);
    pack2(q2, q3, h1, w1);
    uint4 wi; wi.x = h0; wi.y = w0; wi.z = h1; wi.w = w1;
    *(uint4*)(di + (size_t)hh * CH * LL + (size_t)(c0 + c) * LL + (l0 + l4)) = wi;

    tsm[c][l4 + 0] = q0; tsm[c][l4 + 1] = q1;
    tsm[c][l4 + 2] = q2; tsm[c][l4 + 3] = q3;
    __syncthreads();

    const int l = threadIdx.x >> 3, c4 = (threadIdx.x & 7) * 4;
    uint32_t e0 = tsm[c4 + 0][l], e1 = tsm[c4 + 1][l];
    uint32_t e2 = tsm[c4 + 2][l], e3 = tsm[c4 + 3][l];
    uint32_t th0, tl0, th1, tl1;
    pack2(e0, e1, th0, tl0);
    pack2(e2, e3, th1, tl1);
    uint4 wt; wt.x = th0; wt.y = tl0; wt.z = th1; wt.w = tl1;
    *(uint4*)(dTi + (size_t)hh * LL * CH + (size_t)(l0 + l) * CH + c0 + c4) = wt;
}

// elementwise split -> interleaved (conv weight, pairs along contiguous dim)
__global__ __launch_bounds__(256)
void split_ki(const float* __restrict__ in, uint32_t* __restrict__ out) {
    const size_t i = ((size_t)blockIdx.x * 256 + threadIdx.x) * 4;
    float4 x = *(const float4*)(in + i);
    uint32_t q0 = splt(x.x), q1 = splt(x.y), q2 = splt(x.z), q3 = splt(x.w);
    uint32_t h0, l0, h1, l1;
    pack2(q0, q1, h0, l0);
    pack2(q2, q3, h1, l1);
    uint4 o; o.x = h0; o.y = l0; o.z = h1; o.w = l1;
    *(uint4*)(out + i) = o;
}

// ============================================================================
// Row softmax: fp32 W -> interleaved split
// ============================================================================
__global__ __launch_bounds__(256)
void softmax_il() {
    const float* p = g_W + (size_t)blockIdx.x * LL;
    uint32_t* q = g_W2i + (size_t)blockIdx.x * LL;
    const int tid = threadIdx.x;
    float4 v = *(const float4*)(p + tid * 4);

    float m = fmaxf(fmaxf(v.x, v.y), fmaxf(v.z, v.w));
    #pragma unroll
    for (int o = 16; o; o >>= 1) m = fmaxf(m, __shfl_xor_sync(~0u, m, o));
    __shared__ float redm[8], reds[8];
    if ((tid & 31) == 0) redm[tid >> 5] = m;
    __syncthreads();
    float mx = redm[0];
    #pragma unroll
    for (int w = 1; w < 8; w++) mx = fmaxf(mx, redm[w]);

    v.x = expf(v.x - mx); v.y = expf(v.y - mx);
    v.z = expf(v.z - mx); v.w = expf(v.w - mx);
    float s = v.x + v.y + v.z + v.w;
    #pragma unroll
    for (int o = 16; o; o >>= 1) s += __shfl_xor_sync(~0u, s, o);
    if ((tid & 31) == 0) reds[tid >> 5] = s;
    __syncthreads();
    float st = 0.f;
    #pragma unroll
    for (int w = 0; w < 8; w++) st += reds[w];

    float inv = 1.0f / st;
    uint32_t q0 = splt(v.x * inv), q1 = splt(v.y * inv);
    uint32_t q2 = splt(v.z * inv), q3 = splt(v.w * inv);
    uint32_t h0, l0, h1, l1;
    pack2(q0, q1, h0, l0);
    pack2(q2, q3, h1, l1);
    uint4 o; o.x = h0; o.y = l0; o.z = h1; o.w = l1;
    *(uint4*)(q + tid * 4) = o;
}

// ============================================================================
// BN stats + normalize + swish
// ============================================================================
__global__ __launch_bounds__(256)
void bn_stats() {
    const int o = blockIdx.x;
    float s = 0.f, sq = 0.f;
    for (int idx = threadIdx.x; idx < Bb * LL; idx += 256) {
        const int b = idx >> 10, l = idx & (LL - 1);
        float x = g_x[((size_t)b * Cc + o) * LL + l];
        s += x; sq += x * x;
    }
    __shared__ float rs[256], rq[256];
    rs[threadIdx.x] = s; rq[threadIdx.x] = sq;
    __syncthreads();
    for (int st = 128; st; st >>= 1) {
        if (threadIdx.x < st) {
            rs[threadIdx.x] += rs[threadIdx.x + st];
            rq[threadIdx.x] += rq[threadIdx.x + st];
        }
        __syncthreads();
    }
    if (threadIdx.x == 0) {
        const float n = (float)(Bb * LL);
        float mean = rs[0] / n;
        float var  = rq[0] / n - mean * mean;
        g_stats[o] = mean;
        g_stats[Cc + o] = rsqrtf(var + 1e-5f);
    }
}

__global__ __launch_bounds__(256)
void bn_swish(const float* __restrict__ gamma, const float* __restrict__ beta,
              float* __restrict__ out) {
    const size_t i = ((size_t)blockIdx.x * blockDim.x + threadIdx.x) * 4;
    const int o = (int)((i >> 10) & (Cc - 1));
    const float m = g_stats[o], is = g_stats[Cc + o];
    const float ga = gamma[o], be = beta[o];
    float4 x = *(const float4*)(g_x + i);
    float4 y;
    { float xn = (x.x - m) * is * ga + be; y.x = xn / (1.f + expf(-xn)); }
    { float xn = (x.y - m) * is * ga + be; y.y = xn / (1.f + expf(-xn)); }
    { float xn = (x.z - m) * is * ga + be; y.z = xn / (1.f + expf(-xn)); }
    { float xn = (x.w - m) * is * ga + be; y.w = xn / (1.f + expf(-xn)); }
    *(float4*)(out + i) = y;
}

// ============================================================================
// launch
// ============================================================================
extern "C" void kernel_launch(void* const* d_in, const int* in_sizes, int n_in,
                              void* d_out, int out_size) {
    const float* c_in   = (const float*)d_in[0];
    const float* e_in   = (const float*)d_in[1];
    const float* conv_w = (const float*)d_in[2];
    const float* conv_b = (const float*)d_in[3];
    const float* gamma  = (const float*)d_in[4];
    const float* beta   = (const float*)d_in[5];
    float* out = (float*)d_out;

    uint32_t *c2i, *e2i, *c2Ti, *e2Ti, *t12Ti, *t22Ti, *cw2i;
    cudaGetSymbolAddress((void**)&c2i,   g_c2i);
    cudaGetSymbolAddress((void**)&e2i,   g_e2i);
    cudaGetSymbolAddress((void**)&c2Ti,  g_c2Ti);
    cudaGetSymbolAddress((void**)&e2Ti,  g_e2Ti);
    cudaGetSymbolAddress((void**)&t12Ti, g_t12Ti);
    cudaGetSymbolAddress((void**)&t22Ti, g_t22Ti);
    cudaGetSymbolAddress((void**)&cw2i,  g_cw2i);

    cudaFuncSetAttribute(qk_bf,   cudaFuncAttributeMaxDynamicSharedMemorySize, SMEM_TOTAL);
    cudaFuncSetAttribute(av_bf,   cudaFuncAttributeMaxDynamicSharedMemorySize, SMEM_TOTAL);
    cudaFuncSetAttribute(conv_bf, cudaFuncAttributeMaxDynamicSharedMemorySize, SMEM_TOTAL);

    const int NEL = Bb * Cc * LL;   // 4M

    // builders
    split_tr<<<dim3(32, 4, BH), 256>>>(c_in, c2i, c2Ti);
    split_tr<<<dim3(32, 4, BH), 256>>>(e_in, e2i, e2Ti);
    split_ki<<<Cc * Cc / 1024, 256>>>(conv_w, cw2i);

    // attn1: _c = attn(q=e, k=c, v=c)
    qk_bf<<<dim3(8, 8, BH), 256, SMEM_TOTAL>>>(e2Ti, c2Ti);
    softmax_il<<<BH * LL, 256>>>();
    av_bf<<<dim3(8, 1, BH), 256, SMEM_TOTAL>>>(c2i, t12Ti, 128);

    // attn2: _e = attn(q=_c, k=e, v=e)
    qk_bf<<<dim3(8, 8, BH), 256, SMEM_TOTAL>>>(t12Ti, e2Ti);
    softmax_il<<<BH * LL, 256>>>();
    av_bf<<<dim3(8, 1, BH), 256, SMEM_TOTAL>>>(e2i, t22Ti, 512);

    // proj: 1x1 conv + bias, then BN + swish
    conv_bf<<<dim3(8, 4, 8), 256, SMEM_TOTAL>>>(cw2i, t22Ti, conv_b);
    bn_stats<<<Cc, 256>>>();
    bn_swish<<<NEL / 1024, 256>>>(gamma, beta, out);
}